// round 7
// baseline (speedup 1.0000x reference)
#include <cuda_runtime.h>
#include <cfloat>

#define DIM      768
#define QN       64
#define KC       32
#define DT       64
#define NTHREADS 256
#define NBLOCKS  592
#define TOPK     5

// ---------------- device scratch (no allocations allowed) ----------------
__device__ float g_qt_dup[DIM * 2 * QN];                // [d][128], q duplicated pairwise
__device__ float g_cand_val[NBLOCKS * QN * TOPK];
__device__ int   g_cand_idx[NBLOCKS * QN * TOPK];

// ---------------- helpers ----------------
// packed fp32 FMA (sm_103a FFMA2): 2 FMAs per lane per instruction
__device__ __forceinline__ float2 ffma2(float2 a, float2 b, float2 c) {
    unsigned long long ua = *reinterpret_cast<unsigned long long*>(&a);
    unsigned long long ub = *reinterpret_cast<unsigned long long*>(&b);
    unsigned long long uc = *reinterpret_cast<unsigned long long*>(&c);
    unsigned long long ud;
    asm("fma.rn.f32x2 %0, %1, %2, %3;" : "=l"(ud) : "l"(ua), "l"(ub), "l"(uc));
    return *reinterpret_cast<float2*>(&ud);
}

// strict ordering: higher value wins; ties -> lower index (matches lax.top_k)
__device__ __forceinline__ bool better(float av, int ai, float bv, int bi) {
    return (av > bv) || (av == bv && ai < bi);
}

__device__ __forceinline__ void topk_insert(float* tv, int* ti, float s, int idx) {
    if (!better(s, idx, tv[TOPK - 1], ti[TOPK - 1])) return;
    int pos = TOPK - 1;
    #pragma unroll
    for (int it = 0; it < TOPK - 1; it++) {
        if (pos > 0 && better(s, idx, tv[pos - 1], ti[pos - 1])) {
            tv[pos] = tv[pos - 1];
            ti[pos] = ti[pos - 1];
            pos--;
        }
    }
    tv[pos] = s;
    ti[pos] = idx;
}

// ---------------- kernel 1: q = query @ W^T + b, stored transposed + duplicated ----------------
#define QP_KC 64
__global__ __launch_bounds__(256) void qproj_kernel(
    const float* __restrict__ query,   // [QN, DIM]
    const float* __restrict__ W,       // [DIM, DIM]
    const float* __restrict__ bias)    // [DIM]
{
    __shared__ float sW[16][QP_KC];
    __shared__ float sQ[QN][QP_KC + 1];

    int tid = threadIdx.x;
    int dbase = blockIdx.x * 16;
    int q  = tid & 63;
    int dg = tid >> 6;                 // 0..3 -> handles d = dg*4 .. dg*4+3 (local)

    float acc[4] = {0.f, 0.f, 0.f, 0.f};

    for (int kb = 0; kb < DIM; kb += QP_KC) {
        __syncthreads();
        {   // W tile: 16 rows x 64 floats = 256 float4
            int row = tid >> 4;
            int c4  = tid & 15;
            float4 v = *(const float4*)&W[(size_t)(dbase + row) * DIM + kb + c4 * 4];
            sW[row][c4 * 4 + 0] = v.x; sW[row][c4 * 4 + 1] = v.y;
            sW[row][c4 * 4 + 2] = v.z; sW[row][c4 * 4 + 3] = v.w;
        }
        #pragma unroll
        for (int i = 0; i < 4; i++) {  // query tile: 64 x 64 floats = 1024 float4
            int idx = tid + i * 256;
            int row = idx >> 4;
            int c4  = idx & 15;
            float4 v = *(const float4*)&query[(size_t)row * DIM + kb + c4 * 4];
            sQ[row][c4 * 4 + 0] = v.x; sQ[row][c4 * 4 + 1] = v.y;
            sQ[row][c4 * 4 + 2] = v.z; sQ[row][c4 * 4 + 3] = v.w;
        }
        __syncthreads();
        #pragma unroll 8
        for (int k = 0; k < QP_KC; k++) {
            float qv = sQ[q][k];
            #pragma unroll
            for (int i = 0; i < 4; i++) acc[i] += sW[dg * 4 + i][k] * qv;
        }
    }

    #pragma unroll
    for (int i = 0; i < 4; i++) {
        int d = dbase + dg * 4 + i;
        float val = acc[i] + bias[d];
        g_qt_dup[(size_t)d * (2 * QN) + 2 * q]     = val;
        g_qt_dup[(size_t)d * (2 * QN) + 2 * q + 1] = val;
    }
}

// ---------------- kernel 2: scores GEMM (FFMA2) + fused per-block top-5 ----------------
__global__ __launch_bounds__(NTHREADS) void score_topk_kernel(
    const float* __restrict__ emb, int ndocs, int ntiles)
{
    __shared__ float sdoc[KC][DT + 2];      // [k][doc]
    __shared__ float sq[KC][2 * QN];        // duplicated q chunk
    __shared__ float stage[DT][QN + 1];     // per-tile scores for the merge
    __shared__ float topv[QN][TOPK];
    __shared__ int   topi[QN][TOPK];

    int tid = threadIdx.x;
    int tx  = tid & 15;                      // query group: queries tx*4 .. +3
    int ty  = tid >> 4;                      // doc group:   docs    ty*4 .. +3
    int ty4 = ty * 4;
    int tx8 = tx * 8;
    int tx4 = tx * 4;

    if (tid < QN) {
        #pragma unroll
        for (int j = 0; j < TOPK; j++) { topv[tid][j] = -FLT_MAX; topi[tid][j] = 0x7fffffff; }
    }

    for (int t = blockIdx.x; t < ntiles; t += gridDim.x) {
        int docbase = t * DT;

        float2 acc[2][4];
        #pragma unroll
        for (int p = 0; p < 2; p++)
            #pragma unroll
            for (int j = 0; j < 4; j++) acc[p][j] = make_float2(0.f, 0.f);

        for (int kb = 0; kb < DIM; kb += KC) {
            __syncthreads();   // protects stage reads (prev tile) + sdoc/sq reuse
            // doc tile: DT rows x KC floats = 512 float4, stored transposed
            #pragma unroll
            for (int i = 0; i < 2; i++) {
                int idx = tid + i * NTHREADS;     // 0..511
                int row = idx >> 3;               // 8 float4 per row
                int c4  = idx & 7;
                int gdoc = docbase + row;
                float4 v = make_float4(0.f, 0.f, 0.f, 0.f);
                if (gdoc < ndocs)
                    v = *(const float4*)&emb[(size_t)gdoc * DIM + kb + c4 * 4];
                sdoc[c4 * 4 + 0][row] = v.x;
                sdoc[c4 * 4 + 1][row] = v.y;
                sdoc[c4 * 4 + 2][row] = v.z;
                sdoc[c4 * 4 + 3][row] = v.w;
            }
            // duplicated q chunk: KC*128 floats = 1024 float4, contiguous copy
            #pragma unroll
            for (int i = 0; i < 4; i++) {
                int idx = tid + i * NTHREADS;
                float4 v = *(const float4*)&g_qt_dup[(size_t)kb * (2 * QN) + idx * 4];
                *(float4*)&sq[0][idx * 4] = v;
            }
            __syncthreads();

            #pragma unroll
            for (int kk = 0; kk < KC; kk++) {
                float2 dp0 = *(const float2*)&sdoc[kk][ty4];      // (doc0,doc1)
                float2 dp1 = *(const float2*)&sdoc[kk][ty4 + 2];  // (doc2,doc3)
                float4 qa  = *(const float4*)&sq[kk][tx8];        // (q0,q0,q1,q1)
                float4 qb  = *(const float4*)&sq[kk][tx8 + 4];    // (q2,q2,q3,q3)
                acc[0][0] = ffma2(dp0, make_float2(qa.x, qa.y), acc[0][0]);
                acc[1][0] = ffma2(dp1, make_float2(qa.x, qa.y), acc[1][0]);
                acc[0][1] = ffma2(dp0, make_float2(qa.z, qa.w), acc[0][1]);
                acc[1][1] = ffma2(dp1, make_float2(qa.z, qa.w), acc[1][1]);
                acc[0][2] = ffma2(dp0, make_float2(qb.x, qb.y), acc[0][2]);
                acc[1][2] = ffma2(dp1, make_float2(qb.x, qb.y), acc[1][2]);
                acc[0][3] = ffma2(dp0, make_float2(qb.z, qb.w), acc[0][3]);
                acc[1][3] = ffma2(dp1, make_float2(qb.z, qb.w), acc[1][3]);
            }
        }

        __syncthreads();
        // stage: acc[p][j] = scores of docs (ty4+2p, ty4+2p+1) for query tx4+j
        #pragma unroll
        for (int p = 0; p < 2; p++)
            #pragma unroll
            for (int j = 0; j < 4; j++) {
                stage[ty4 + 2 * p][tx4 + j]     = acc[p][j].x;
                stage[ty4 + 2 * p + 1][tx4 + j] = acc[p][j].y;
            }
        __syncthreads();

        if (tid < QN) {
            int q = tid;
            float* tv = topv[q];
            int*   ti = topi[q];
            int dmax = ndocs - docbase;
            if (dmax > DT) dmax = DT;
            for (int dl = 0; dl < dmax; dl++) {
                float s = stage[dl][q];
                if (s > tv[TOPK - 1]) topk_insert(tv, ti, s, docbase + dl);
            }
        }
    }

    __syncthreads();
    if (tid < QN) {
        #pragma unroll
        for (int j = 0; j < TOPK; j++) {
            size_t o = ((size_t)blockIdx.x * QN + tid) * TOPK + j;
            g_cand_val[o] = topv[tid][j];
            g_cand_idx[o] = topi[tid][j];
        }
    }
}

// ---------------- kernel 3: global candidate merge -> output (FLOAT indices) ----------------
// __output__ dtype is float32: rel_err was exactly 1.0 for three rounds because
// int32 index writes reinterpret as float denormals (~0). Write (float)index.
__global__ __launch_bounds__(128) void final_topk_kernel(float* __restrict__ out, int nblocks)
{
    __shared__ float sval[128 * TOPK];
    __shared__ int   sidx[128 * TOPK];
    int q   = blockIdx.x;
    int tid = threadIdx.x;

    float lv[TOPK]; int li[TOPK];
    #pragma unroll
    for (int j = 0; j < TOPK; j++) { lv[j] = -FLT_MAX; li[j] = 0x7fffffff; }

    for (int b = tid; b < nblocks; b += 128) {
        size_t o = ((size_t)b * QN + q) * TOPK;
        #pragma unroll
        for (int j = 0; j < TOPK; j++)
            topk_insert(lv, li, g_cand_val[o + j], g_cand_idx[o + j]);
    }
    #pragma unroll
    for (int j = 0; j < TOPK; j++) { sval[tid * TOPK + j] = lv[j]; sidx[tid * TOPK + j] = li[j]; }
    __syncthreads();

    if (tid == 0) {
        float fv[TOPK]; int fi[TOPK];
        #pragma unroll
        for (int j = 0; j < TOPK; j++) { fv[j] = -FLT_MAX; fi[j] = 0x7fffffff; }
        for (int e = 0; e < 128 * TOPK; e++)
            topk_insert(fv, fi, sval[e], sidx[e]);
        #pragma unroll
        for (int j = 0; j < TOPK; j++) out[q * TOPK + j] = (float)fi[j];
    }
}

// ---------------- launch ----------------
// Inputs identified BY ELEMENT COUNT (robust to metadata.txt ordering):
//   b = 768, query = 49152, W = 589824, block_emb = largest, top_k scalar ignored.
extern "C" void kernel_launch(void* const* d_in, const int* in_sizes, int n_in,
                              void* d_out, int out_size)
{
    const float* query = nullptr;
    const float* W     = nullptr;
    const float* bias  = nullptr;
    const float* emb   = nullptr;
    int ndocs = 0;

    for (int i = 0; i < n_in; i++) {
        int sz = in_sizes[i];
        if (sz == DIM) {
            bias = (const float*)d_in[i];
        } else if (sz == QN * DIM) {
            query = (const float*)d_in[i];
        } else if (sz == DIM * DIM) {
            W = (const float*)d_in[i];
        } else if (sz > DIM * DIM) {
            emb = (const float*)d_in[i];
            ndocs = sz / DIM;
        }
    }
    if (!query || !W || !bias || !emb || ndocs <= 0) return;

    int ntiles = (ndocs + DT - 1) / DT;

    qproj_kernel<<<DIM / 16, 256>>>(query, W, bias);
    score_topk_kernel<<<NBLOCKS, NTHREADS>>>(emb, ndocs, ntiles);
    final_topk_kernel<<<QN, 128>>>((float*)d_out, NBLOCKS);
}

// round 10
// speedup vs baseline: 3.5478x; 3.5478x over previous
#include <cuda_runtime.h>
#include <cuda_bf16.h>
#include <cfloat>
#include <cstdint>

#define DIM      768
#define QN       64
#define TILE_M   128
#define CHUNK_K  64
#define NCHUNK   (DIM / CHUNK_K)     // 12
#define KSTEPS   (CHUNK_K / 16)      // 4
#define NTHREADS 256
#define NBLOCKS  304                 // 2 per SM x 152 SMs
#define TOPK     5

// ---- smem pool layout (offsets from 1024-aligned base) ----
#define A_TILE_BYTES (TILE_M * 128)             // 16384: 128 m-rows x 64 bf16 (128B, SW128)
#define B_TILE_BYTES (CHUNK_K * 128)            // 8192:  64 k-rows x 64 bf16 (128B, SW128)
#define OFF_A        0
#define OFF_B        (3 * A_TILE_BYTES)         // 49152
#define SMEM_DYN     (OFF_B + 3 * B_TILE_BYTES + 1024)   // 74752 (+align slack)
#define STAGE_STRIDE 68                         // floats (stage aliases A region)

// ---------------- device scratch (no allocations allowed) ----------------
__device__ uint4 g_qb_u4[3][DIM * QN / 8];      // bf16 q-splits, [s][d][q] (d-major, 128B rows)
__device__ float g_cand_val[NBLOCKS * QN * TOPK];
__device__ int   g_cand_idx[NBLOCKS * QN * TOPK];

// ---------------- helpers ----------------
__device__ __forceinline__ uint32_t smem_u32(const void* p) {
    uint32_t a;
    asm("{ .reg .u64 t; cvta.to.shared.u64 t, %1; cvt.u32.u64 %0, t; }" : "=r"(a) : "l"(p));
    return a;
}
#define SW128(off) ((off) ^ (((off) >> 3) & 0x70))

__device__ __forceinline__ void ldsm_x4(uint32_t* r, uint32_t addr) {
    asm volatile("ldmatrix.sync.aligned.m8n8.x4.shared.b16 {%0,%1,%2,%3}, [%4];"
        : "=r"(r[0]), "=r"(r[1]), "=r"(r[2]), "=r"(r[3]) : "r"(addr));
}
__device__ __forceinline__ void ldsm_x4_t(uint32_t* r, uint32_t addr) {
    asm volatile("ldmatrix.sync.aligned.m8n8.x4.trans.shared.b16 {%0,%1,%2,%3}, [%4];"
        : "=r"(r[0]), "=r"(r[1]), "=r"(r[2]), "=r"(r[3]) : "r"(addr));
}
__device__ __forceinline__ void mma_bf16(float* d, const uint32_t* a, const uint32_t* b) {
    asm volatile("mma.sync.aligned.m16n8k16.row.col.f32.bf16.bf16.f32 "
        "{%0,%1,%2,%3}, {%4,%5,%6,%7}, {%8,%9}, {%0,%1,%2,%3};"
        : "+f"(d[0]), "+f"(d[1]), "+f"(d[2]), "+f"(d[3])
        : "r"(a[0]), "r"(a[1]), "r"(a[2]), "r"(a[3]), "r"(b[0]), "r"(b[1]));
}

// strict ordering: higher value wins; ties -> lower index (matches lax.top_k)
__device__ __forceinline__ bool better(float av, int ai, float bv, int bi) {
    return (av > bv) || (av == bv && ai < bi);
}
__device__ __forceinline__ void topk_insert(float* tv, int* ti, float s, int idx) {
    if (!better(s, idx, tv[TOPK - 1], ti[TOPK - 1])) return;
    int pos = TOPK - 1;
    #pragma unroll
    for (int it = 0; it < TOPK - 1; it++) {
        if (pos > 0 && better(s, idx, tv[pos - 1], ti[pos - 1])) {
            tv[pos] = tv[pos - 1]; ti[pos] = ti[pos - 1]; pos--;
        }
    }
    tv[pos] = s; ti[pos] = idx;
}

// ---------------- kernel 1: q = query @ W^T + b -> 3 bf16 splits, [s][d][q] ----------------
#define QP_KC 64
__global__ __launch_bounds__(256) void qproj_kernel(
    const float* __restrict__ query, const float* __restrict__ W, const float* __restrict__ bias)
{
    __shared__ float sW[16][QP_KC];
    __shared__ float sQ[QN][QP_KC + 1];

    int tid = threadIdx.x;
    int dbase = blockIdx.x * 16;
    int q  = tid & 63;
    int dg = tid >> 6;

    float acc[4] = {0.f, 0.f, 0.f, 0.f};

    for (int kb = 0; kb < DIM; kb += QP_KC) {
        __syncthreads();
        {
            int row = tid >> 4, c4 = tid & 15;
            float4 v = *(const float4*)&W[(size_t)(dbase + row) * DIM + kb + c4 * 4];
            sW[row][c4*4+0]=v.x; sW[row][c4*4+1]=v.y; sW[row][c4*4+2]=v.z; sW[row][c4*4+3]=v.w;
        }
        #pragma unroll
        for (int i = 0; i < 4; i++) {
            int idx = tid + i * 256;
            int row = idx >> 4, c4 = idx & 15;
            float4 v = *(const float4*)&query[(size_t)row * DIM + kb + c4 * 4];
            sQ[row][c4*4+0]=v.x; sQ[row][c4*4+1]=v.y; sQ[row][c4*4+2]=v.z; sQ[row][c4*4+3]=v.w;
        }
        __syncthreads();
        #pragma unroll 8
        for (int k = 0; k < QP_KC; k++) {
            float qv = sQ[q][k];
            #pragma unroll
            for (int i = 0; i < 4; i++) acc[i] += sW[dg * 4 + i][k] * qv;
        }
    }

    unsigned short* qb = (unsigned short*)g_qb_u4;   // [s][d][q]
    #pragma unroll
    for (int i = 0; i < 4; i++) {
        int d = dbase + dg * 4 + i;
        float val = acc[i] + bias[d];
        uint32_t vb = __float_as_uint(val);
        unsigned short hi = (unsigned short)(vb >> 16);
        float r = val - __uint_as_float(vb & 0xFFFF0000u);      // exact residual
        uint32_t rb = __float_as_uint(r);
        unsigned short mid = (unsigned short)(rb >> 16);
        float r2 = r - __uint_as_float(rb & 0xFFFF0000u);       // exact residual
        unsigned short lo = __bfloat16_as_ushort(__float2bfloat16(r2));
        qb[(size_t)(0 * DIM + d) * QN + q] = hi;
        qb[(size_t)(1 * DIM + d) * QN + q] = mid;
        qb[(size_t)(2 * DIM + d) * QN + q] = lo;
    }
}

// ---------------- kernel 2: mma.sync bf16-split scores + fused per-block top-5 ----------------
__global__ __launch_bounds__(NTHREADS, 2) void score_topk_kernel(
    const float* __restrict__ emb, int ndocs, int ntiles)
{
    extern __shared__ char dynsmem[];
    __shared__ float topv[QN][TOPK];
    __shared__ int   topi[QN][TOPK];

    int tid  = threadIdx.x;
    int lane = tid & 31;
    int w    = tid >> 5;
    int m_base = (w >> 1) * 32;
    int n_base = (w & 1) * 32;

    uint32_t raw  = smem_u32(dynsmem);
    uint32_t base = (raw + 1023) & ~1023u;
    char*    pool = dynsmem + (base - raw);
    uint32_t aBase = base + OFF_A;
    uint32_t bBase = base + OFF_B;
    float*   stage = (float*)(pool + OFF_A);   // aliases A tiles (guarded by barriers)

    if (tid < QN) {
        #pragma unroll
        for (int j = 0; j < TOPK; j++) { topv[tid][j] = -FLT_MAX; topi[tid][j] = 0x7fffffff; }
    }

    // ldmatrix per-lane row/col components (same pattern for A and B x4 loads)
    int l15 = lane & 15;          // row within 16-row group
    int lh8 = (lane >> 4) * 8;    // 8-col offset for upper half of lanes

    for (int t = blockIdx.x; t < ntiles; t += gridDim.x) {
        int docbase = t * TILE_M;

        float acc[2][4][4];
        #pragma unroll
        for (int mi = 0; mi < 2; mi++)
            #pragma unroll
            for (int ni = 0; ni < 4; ni++)
                #pragma unroll
                for (int r = 0; r < 4; r++) acc[mi][ni][r] = 0.f;

        for (int c = 0; c < NCHUNK; c++) {
            int kb = c * CHUNK_K;
            __syncthreads();   // writers wait for readers of previous chunk / stage

            // ---- A: fp32 [128m x 64k] -> 3 bf16 SW128 tiles ----
            #pragma unroll
            for (int i = 0; i < 8; i++) {
                int idx = tid + i * NTHREADS;     // 0..2047 float4 slots
                int row = idx >> 4;
                int c4  = idx & 15;
                int gdoc = docbase + row;
                float4 v = make_float4(0.f, 0.f, 0.f, 0.f);
                if (gdoc < ndocs)
                    v = *(const float4*)&emb[(size_t)gdoc * DIM + kb + c4 * 4];
                uint32_t x0 = __float_as_uint(v.x), x1 = __float_as_uint(v.y);
                uint32_t x2 = __float_as_uint(v.z), x3 = __float_as_uint(v.w);
                uint32_t hiA = __byte_perm(x0, x1, 0x7632);
                uint32_t hiB = __byte_perm(x2, x3, 0x7632);
                float r0 = v.x - __uint_as_float(x0 & 0xFFFF0000u);
                float r1 = v.y - __uint_as_float(x1 & 0xFFFF0000u);
                float r2 = v.z - __uint_as_float(x2 & 0xFFFF0000u);
                float r3 = v.w - __uint_as_float(x3 & 0xFFFF0000u);
                uint32_t rb0 = __float_as_uint(r0), rb1 = __float_as_uint(r1);
                uint32_t rb2 = __float_as_uint(r2), rb3 = __float_as_uint(r3);
                uint32_t miA = __byte_perm(rb0, rb1, 0x7632);
                uint32_t miB = __byte_perm(rb2, rb3, 0x7632);
                float s0 = r0 - __uint_as_float(rb0 & 0xFFFF0000u);
                float s1 = r1 - __uint_as_float(rb1 & 0xFFFF0000u);
                float s2 = r2 - __uint_as_float(rb2 & 0xFFFF0000u);
                float s3 = r3 - __uint_as_float(rb3 & 0xFFFF0000u);
                uint32_t loA, loB;
                asm("cvt.rn.bf16x2.f32 %0, %1, %2;" : "=r"(loA) : "f"(s1), "f"(s0));
                asm("cvt.rn.bf16x2.f32 %0, %1, %2;" : "=r"(loB) : "f"(s3), "f"(s2));
                uint32_t off = SW128((uint32_t)(row * 128 + c4 * 8));
                *(uint2*)(pool + OFF_A + 0 * A_TILE_BYTES + off) = make_uint2(hiA, hiB);
                *(uint2*)(pool + OFF_A + 1 * A_TILE_BYTES + off) = make_uint2(miA, miB);
                *(uint2*)(pool + OFF_A + 2 * A_TILE_BYTES + off) = make_uint2(loA, loB);
            }

            // ---- B: copy 3 q-split chunks [64k x 64q] (already bf16, d-major) ----
            #pragma unroll
            for (int i = 0; i < 6; i++) {
                int lin = tid + i * NTHREADS;     // 0..1535 uint4 slots
                int s   = lin >> 9;
                int rem = lin & 511;
                int r   = rem >> 3;
                int cc  = rem & 7;
                uint4 v = g_qb_u4[0][(size_t)(s * DIM + kb + r) * 8 + cc];
                *(uint4*)(pool + OFF_B + s * B_TILE_BYTES + SW128((uint32_t)(r * 128 + cc * 16))) = v;
            }
            __syncthreads();

            // ---- MMA: per k16-step load frags for all 3 splits, run 6 term-MMAs ----
            #pragma unroll
            for (int ks = 0; ks < KSTEPS; ks++) {
                uint32_t Af[3][2][4];
                uint32_t Bf[3][8];
                uint32_t aoff0 = SW128((uint32_t)((m_base + l15) * 128 + (ks * 16 + lh8) * 2));
                uint32_t aoff1 = SW128((uint32_t)((m_base + 16 + l15) * 128 + (ks * 16 + lh8) * 2));
                uint32_t boff0 = SW128((uint32_t)((ks * 16 + l15) * 128 + (n_base + lh8) * 2));
                uint32_t boff1 = SW128((uint32_t)((ks * 16 + l15) * 128 + (n_base + 16 + lh8) * 2));
                #pragma unroll
                for (int s = 0; s < 3; s++) {
                    ldsm_x4  (Af[s][0],  aBase + s * A_TILE_BYTES + aoff0);
                    ldsm_x4  (Af[s][1],  aBase + s * A_TILE_BYTES + aoff1);
                    ldsm_x4_t(&Bf[s][0], bBase + s * B_TILE_BYTES + boff0);
                    ldsm_x4_t(&Bf[s][4], bBase + s * B_TILE_BYTES + boff1);
                }
                const int sa[6] = {0, 0, 1, 0, 2, 1};
                const int sb[6] = {0, 1, 0, 2, 0, 1};
                #pragma unroll
                for (int p = 0; p < 6; p++)
                    #pragma unroll
                    for (int mi = 0; mi < 2; mi++)
                        #pragma unroll
                        for (int ni = 0; ni < 4; ni++)
                            mma_bf16(acc[mi][ni], Af[sa[p]][mi], &Bf[sb[p]][ni * 2]);
            }
        }

        // ---- epilogue: acc -> stage (A alias) -> per-query top-5 ----
        __syncthreads();
        #pragma unroll
        for (int mi = 0; mi < 2; mi++)
            #pragma unroll
            for (int ni = 0; ni < 4; ni++) {
                int row = m_base + mi * 16 + (lane >> 2);
                int col = n_base + ni * 8 + (lane & 3) * 2;
                *(float2*)&stage[row * STAGE_STRIDE + col] =
                    make_float2(acc[mi][ni][0], acc[mi][ni][1]);
                *(float2*)&stage[(row + 8) * STAGE_STRIDE + col] =
                    make_float2(acc[mi][ni][2], acc[mi][ni][3]);
            }
        __syncthreads();
        if (tid < QN) {
            float* tv = topv[tid];
            int*   ti = topi[tid];
            int dmax = ndocs - docbase;
            if (dmax > TILE_M) dmax = TILE_M;
            for (int dl = 0; dl < dmax; dl++) {
                float s = stage[dl * STAGE_STRIDE + tid];
                if (s > tv[TOPK - 1]) topk_insert(tv, ti, s, docbase + dl);
            }
        }
        // next tile's first __syncthreads() protects stage before A stores
    }

    __syncthreads();
    if (tid < QN) {
        #pragma unroll
        for (int j = 0; j < TOPK; j++) {
            size_t o = ((size_t)blockIdx.x * QN + tid) * TOPK + j;
            g_cand_val[o] = topv[tid][j];
            g_cand_idx[o] = topi[tid][j];
        }
    }
}

// ---------------- kernel 3: global candidate merge -> output (float indices) ----------------
__global__ __launch_bounds__(128) void final_topk_kernel(float* __restrict__ out, int nblocks)
{
    __shared__ float sval[128 * TOPK];
    __shared__ int   sidx[128 * TOPK];
    int q   = blockIdx.x;
    int tid = threadIdx.x;

    float lv[TOPK]; int li[TOPK];
    #pragma unroll
    for (int j = 0; j < TOPK; j++) { lv[j] = -FLT_MAX; li[j] = 0x7fffffff; }

    for (int b = tid; b < nblocks; b += 128) {
        size_t o = ((size_t)b * QN + q) * TOPK;
        #pragma unroll
        for (int j = 0; j < TOPK; j++)
            topk_insert(lv, li, g_cand_val[o + j], g_cand_idx[o + j]);
    }
    #pragma unroll
    for (int j = 0; j < TOPK; j++) { sval[tid * TOPK + j] = lv[j]; sidx[tid * TOPK + j] = li[j]; }
    __syncthreads();

    if (tid == 0) {
        float fv[TOPK]; int fi[TOPK];
        #pragma unroll
        for (int j = 0; j < TOPK; j++) { fv[j] = -FLT_MAX; fi[j] = 0x7fffffff; }
        for (int e = 0; e < 128 * TOPK; e++)
            topk_insert(fv, fi, sval[e], sidx[e]);
        #pragma unroll
        for (int j = 0; j < TOPK; j++) out[q * TOPK + j] = (float)fi[j];
    }
}

// ---------------- launch ----------------
// Inputs identified BY ELEMENT COUNT:
//   b = 768, query = 49152, W = 589824, block_emb = largest, top_k scalar ignored (TOPK=5 per out_size).
extern "C" void kernel_launch(void* const* d_in, const int* in_sizes, int n_in,
                              void* d_out, int out_size)
{
    const float *query = nullptr, *W = nullptr, *bias = nullptr, *emb = nullptr;
    int ndocs = 0;
    for (int i = 0; i < n_in; i++) {
        int sz = in_sizes[i];
        if      (sz == DIM)        bias  = (const float*)d_in[i];
        else if (sz == QN * DIM)   query = (const float*)d_in[i];
        else if (sz == DIM * DIM)  W     = (const float*)d_in[i];
        else if (sz >  DIM * DIM) { emb  = (const float*)d_in[i]; ndocs = sz / DIM; }
    }
    if (!query || !W || !bias || !emb || ndocs <= 0) return;

    int ntiles = (ndocs + TILE_M - 1) / TILE_M;

    cudaFuncSetAttribute(score_topk_kernel, cudaFuncAttributeMaxDynamicSharedMemorySize, SMEM_DYN);

    qproj_kernel<<<DIM / 16, 256>>>(query, W, bias);
    score_topk_kernel<<<NBLOCKS, NTHREADS, SMEM_DYN>>>(emb, ndocs, ntiles);
    final_topk_kernel<<<QN, 128>>>((float*)d_out, NBLOCKS);
}

// round 11
// speedup vs baseline: 5.2048x; 1.4671x over previous
#include <cuda_runtime.h>
#include <cuda_fp16.h>
#include <cfloat>
#include <cstdint>

#define DIM      768
#define QN       64
#define TILE_M   128
#define CHUNK_K  64
#define NCHUNK   (DIM / CHUNK_K)     // 12
#define KSTEPS   (CHUNK_K / 16)      // 4
#define NTHREADS 256
#define NBLOCKS  304                 // 2 per SM x 152 SMs
#define TOPK     5

// ---- smem pool layout (offsets from 1024-aligned base) ----
#define A_TILE_BYTES (TILE_M * 128)             // 16384: 128 m-rows x 64 fp16 (128B, SW128)
#define B_TILE_BYTES (CHUNK_K * 128)            // 8192:  64 k-rows x 64 fp16 (128B, SW128)
#define OFF_A        0
#define OFF_B        (2 * A_TILE_BYTES)         // 32768
#define SMEM_DYN     (OFF_B + 2 * B_TILE_BYTES + 1024)   // 50176 (+align slack)
#define STAGE_STRIDE 68                         // floats; stage spans A tiles + start of B (barrier-safe)

// ---------------- device scratch (no allocations allowed) ----------------
__device__ uint4 g_qh_u4[2][DIM * QN / 8];      // fp16 q-splits, [s][d][q] (d-major, 128B rows)
__device__ float g_cand_val[NBLOCKS * QN * TOPK];
__device__ int   g_cand_idx[NBLOCKS * QN * TOPK];

// ---------------- helpers ----------------
__device__ __forceinline__ uint32_t smem_u32(const void* p) {
    uint32_t a;
    asm("{ .reg .u64 t; cvta.to.shared.u64 t, %1; cvt.u32.u64 %0, t; }" : "=r"(a) : "l"(p));
    return a;
}
#define SW128(off) ((off) ^ (((off) >> 3) & 0x70))

__device__ __forceinline__ void ldsm_x4(uint32_t* r, uint32_t addr) {
    asm volatile("ldmatrix.sync.aligned.m8n8.x4.shared.b16 {%0,%1,%2,%3}, [%4];"
        : "=r"(r[0]), "=r"(r[1]), "=r"(r[2]), "=r"(r[3]) : "r"(addr));
}
__device__ __forceinline__ void ldsm_x4_t(uint32_t* r, uint32_t addr) {
    asm volatile("ldmatrix.sync.aligned.m8n8.x4.trans.shared.b16 {%0,%1,%2,%3}, [%4];"
        : "=r"(r[0]), "=r"(r[1]), "=r"(r[2]), "=r"(r[3]) : "r"(addr));
}
__device__ __forceinline__ void mma_fp16(float* d, const uint32_t* a, const uint32_t* b) {
    asm volatile("mma.sync.aligned.m16n8k16.row.col.f32.f16.f16.f32 "
        "{%0,%1,%2,%3}, {%4,%5,%6,%7}, {%8,%9}, {%0,%1,%2,%3};"
        : "+f"(d[0]), "+f"(d[1]), "+f"(d[2]), "+f"(d[3])
        : "r"(a[0]), "r"(a[1]), "r"(a[2]), "r"(a[3]), "r"(b[0]), "r"(b[1]));
}

// strict ordering: higher value wins; ties -> lower index (matches lax.top_k)
__device__ __forceinline__ bool better(float av, int ai, float bv, int bi) {
    return (av > bv) || (av == bv && ai < bi);
}
__device__ __forceinline__ void topk_insert(float* tv, int* ti, float s, int idx) {
    if (!better(s, idx, tv[TOPK - 1], ti[TOPK - 1])) return;
    int pos = TOPK - 1;
    #pragma unroll
    for (int it = 0; it < TOPK - 1; it++) {
        if (pos > 0 && better(s, idx, tv[pos - 1], ti[pos - 1])) {
            tv[pos] = tv[pos - 1]; ti[pos] = ti[pos - 1]; pos--;
        }
    }
    tv[pos] = s; ti[pos] = idx;
}

// ---------------- kernel 1: q = query @ W^T + b -> 2 fp16 splits (rounded), [s][d][q] ----------------
#define QP_KC 64
__global__ __launch_bounds__(256) void qproj_kernel(
    const float* __restrict__ query, const float* __restrict__ W, const float* __restrict__ bias)
{
    __shared__ float sW[16][QP_KC];
    __shared__ float sQ[QN][QP_KC + 1];

    int tid = threadIdx.x;
    int dbase = blockIdx.x * 16;
    int q  = tid & 63;
    int dg = tid >> 6;

    float acc[4] = {0.f, 0.f, 0.f, 0.f};

    for (int kb = 0; kb < DIM; kb += QP_KC) {
        __syncthreads();
        {
            int row = tid >> 4, c4 = tid & 15;
            float4 v = *(const float4*)&W[(size_t)(dbase + row) * DIM + kb + c4 * 4];
            sW[row][c4*4+0]=v.x; sW[row][c4*4+1]=v.y; sW[row][c4*4+2]=v.z; sW[row][c4*4+3]=v.w;
        }
        #pragma unroll
        for (int i = 0; i < 4; i++) {
            int idx = tid + i * 256;
            int row = idx >> 4, c4 = idx & 15;
            float4 v = *(const float4*)&query[(size_t)row * DIM + kb + c4 * 4];
            sQ[row][c4*4+0]=v.x; sQ[row][c4*4+1]=v.y; sQ[row][c4*4+2]=v.z; sQ[row][c4*4+3]=v.w;
        }
        __syncthreads();
        #pragma unroll 8
        for (int k = 0; k < QP_KC; k++) {
            float qv = sQ[q][k];
            #pragma unroll
            for (int i = 0; i < 4; i++) acc[i] += sW[dg * 4 + i][k] * qv;
        }
    }

    unsigned short* qh = (unsigned short*)g_qh_u4;   // [s][d][q]
    #pragma unroll
    for (int i = 0; i < 4; i++) {
        int d = dbase + dg * 4 + i;
        float val = acc[i] + bias[d];
        __half h = __float2half_rn(val);
        float r  = val - __half2float(h);            // exact residual (Sterbenz)
        __half m = __float2half_rn(r);
        qh[(size_t)(0 * DIM + d) * QN + q] = __half_as_ushort(h);
        qh[(size_t)(1 * DIM + d) * QN + q] = __half_as_ushort(m);
    }
}

// ---------------- kernel 2: fp16 2-split (3-term) mma.sync scores + fused top-5 ----------------
__global__ __launch_bounds__(NTHREADS, 2) void score_topk_kernel(
    const float* __restrict__ emb, int ndocs, int ntiles)
{
    extern __shared__ char dynsmem[];
    __shared__ float topv[QN][TOPK];
    __shared__ int   topi[QN][TOPK];

    int tid  = threadIdx.x;
    int lane = tid & 31;
    int w    = tid >> 5;
    int m_base = (w >> 1) * 32;
    int n_base = (w & 1) * 32;

    uint32_t raw  = smem_u32(dynsmem);
    uint32_t base = (raw + 1023) & ~1023u;
    char*    pool = dynsmem + (base - raw);
    uint32_t aBase = base + OFF_A;
    uint32_t bBase = base + OFF_B;
    float*   stage = (float*)(pool + OFF_A);   // spans A tiles + start of B (guarded by barriers)

    if (tid < QN) {
        #pragma unroll
        for (int j = 0; j < TOPK; j++) { topv[tid][j] = -FLT_MAX; topi[tid][j] = 0x7fffffff; }
    }

    int l15 = lane & 15;
    int lh8 = (lane >> 4) * 8;

    for (int t = blockIdx.x; t < ntiles; t += gridDim.x) {
        int docbase = t * TILE_M;

        float acc[2][4][4];
        #pragma unroll
        for (int mi = 0; mi < 2; mi++)
            #pragma unroll
            for (int ni = 0; ni < 4; ni++)
                #pragma unroll
                for (int r = 0; r < 4; r++) acc[mi][ni][r] = 0.f;

        for (int c = 0; c < NCHUNK; c++) {
            int kb = c * CHUNK_K;
            __syncthreads();   // writers wait for readers of previous chunk / stage

            // ---- A: fp32 [128m x 64k] -> 2 fp16 SW128 tiles (rounded split) ----
            #pragma unroll
            for (int i = 0; i < 8; i++) {
                int idx = tid + i * NTHREADS;     // 0..2047 float4 slots
                int row = idx >> 4;
                int c4  = idx & 15;
                int gdoc = docbase + row;
                float4 v = make_float4(0.f, 0.f, 0.f, 0.f);
                if (gdoc < ndocs)
                    v = *(const float4*)&emb[(size_t)gdoc * DIM + kb + c4 * 4];
                __half2 hA = __floats2half2_rn(v.x, v.y);
                __half2 hB = __floats2half2_rn(v.z, v.w);
                float r0 = v.x - __low2float(hA);
                float r1 = v.y - __high2float(hA);
                float r2 = v.z - __low2float(hB);
                float r3 = v.w - __high2float(hB);
                __half2 mA = __floats2half2_rn(r0, r1);
                __half2 mB = __floats2half2_rn(r2, r3);
                uint32_t off = SW128((uint32_t)(row * 128 + c4 * 8));
                *(uint2*)(pool + OFF_A + 0 * A_TILE_BYTES + off) =
                    make_uint2(*(uint32_t*)&hA, *(uint32_t*)&hB);
                *(uint2*)(pool + OFF_A + 1 * A_TILE_BYTES + off) =
                    make_uint2(*(uint32_t*)&mA, *(uint32_t*)&mB);
            }

            // ---- B: copy 2 q-split chunks [64k x 64q] (already fp16, d-major) ----
            #pragma unroll
            for (int i = 0; i < 4; i++) {
                int lin = tid + i * NTHREADS;     // 0..1023 uint4 slots
                int s   = lin >> 9;
                int rem = lin & 511;
                int r   = rem >> 3;
                int cc  = rem & 7;
                uint4 v = g_qh_u4[0][(size_t)(s * DIM + kb + r) * 8 + cc];
                *(uint4*)(pool + OFF_B + s * B_TILE_BYTES + SW128((uint32_t)(r * 128 + cc * 16))) = v;
            }
            __syncthreads();

            // ---- MMA: per k16-step load frags for both splits, run 3 term-MMAs ----
            #pragma unroll
            for (int ks = 0; ks < KSTEPS; ks++) {
                uint32_t Af[2][2][4];
                uint32_t Bf[2][8];
                uint32_t aoff0 = SW128((uint32_t)((m_base + l15) * 128 + (ks * 16 + lh8) * 2));
                uint32_t aoff1 = SW128((uint32_t)((m_base + 16 + l15) * 128 + (ks * 16 + lh8) * 2));
                uint32_t boff0 = SW128((uint32_t)((ks * 16 + l15) * 128 + (n_base + lh8) * 2));
                uint32_t boff1 = SW128((uint32_t)((ks * 16 + l15) * 128 + (n_base + 16 + lh8) * 2));
                #pragma unroll
                for (int s = 0; s < 2; s++) {
                    ldsm_x4  (Af[s][0],  aBase + s * A_TILE_BYTES + aoff0);
                    ldsm_x4  (Af[s][1],  aBase + s * A_TILE_BYTES + aoff1);
                    ldsm_x4_t(&Bf[s][0], bBase + s * B_TILE_BYTES + boff0);
                    ldsm_x4_t(&Bf[s][4], bBase + s * B_TILE_BYTES + boff1);
                }
                const int sa[3] = {0, 0, 1};   // hh, hm, mh
                const int sb[3] = {0, 1, 0};
                #pragma unroll
                for (int p = 0; p < 3; p++)
                    #pragma unroll
                    for (int mi = 0; mi < 2; mi++)
                        #pragma unroll
                        for (int ni = 0; ni < 4; ni++)
                            mma_fp16(acc[mi][ni], Af[sa[p]][mi], &Bf[sb[p]][ni * 2]);
            }
        }

        // ---- epilogue: acc -> stage -> per-query top-5 ----
        __syncthreads();
        #pragma unroll
        for (int mi = 0; mi < 2; mi++)
            #pragma unroll
            for (int ni = 0; ni < 4; ni++) {
                int row = m_base + mi * 16 + (lane >> 2);
                int col = n_base + ni * 8 + (lane & 3) * 2;
                *(float2*)&stage[row * STAGE_STRIDE + col] =
                    make_float2(acc[mi][ni][0], acc[mi][ni][1]);
                *(float2*)&stage[(row + 8) * STAGE_STRIDE + col] =
                    make_float2(acc[mi][ni][2], acc[mi][ni][3]);
            }
        __syncthreads();
        if (tid < QN) {
            float* tv = topv[tid];
            int*   ti = topi[tid];
            int dmax = ndocs - docbase;
            if (dmax > TILE_M) dmax = TILE_M;
            for (int dl = 0; dl < dmax; dl++) {
                float s = stage[dl * STAGE_STRIDE + tid];
                if (s > tv[TOPK - 1]) topk_insert(tv, ti, s, docbase + dl);
            }
        }
        // next tile's first __syncthreads() protects stage before A/B stores
    }

    __syncthreads();
    if (tid < QN) {
        #pragma unroll
        for (int j = 0; j < TOPK; j++) {
            size_t o = ((size_t)blockIdx.x * QN + tid) * TOPK + j;
            g_cand_val[o] = topv[tid][j];
            g_cand_idx[o] = topi[tid][j];
        }
    }
}

// ---------------- kernel 3: global candidate merge -> output (float indices) ----------------
__global__ __launch_bounds__(128) void final_topk_kernel(float* __restrict__ out, int nblocks)
{
    __shared__ float sval[128 * TOPK];
    __shared__ int   sidx[128 * TOPK];
    int q   = blockIdx.x;
    int tid = threadIdx.x;

    float lv[TOPK]; int li[TOPK];
    #pragma unroll
    for (int j = 0; j < TOPK; j++) { lv[j] = -FLT_MAX; li[j] = 0x7fffffff; }

    for (int b = tid; b < nblocks; b += 128) {
        size_t o = ((size_t)b * QN + q) * TOPK;
        #pragma unroll
        for (int j = 0; j < TOPK; j++)
            topk_insert(lv, li, g_cand_val[o + j], g_cand_idx[o + j]);
    }
    #pragma unroll
    for (int j = 0; j < TOPK; j++) { sval[tid * TOPK + j] = lv[j]; sidx[tid * TOPK + j] = li[j]; }
    __syncthreads();

    if (tid == 0) {
        float fv[TOPK]; int fi[TOPK];
        #pragma unroll
        for (int j = 0; j < TOPK; j++) { fv[j] = -FLT_MAX; fi[j] = 0x7fffffff; }
        for (int e = 0; e < 128 * TOPK; e++)
            topk_insert(fv, fi, sval[e], sidx[e]);
        #pragma unroll
        for (int j = 0; j < TOPK; j++) out[q * TOPK + j] = (float)fi[j];
    }
}

// ---------------- launch ----------------
// Inputs identified BY ELEMENT COUNT:
//   b = 768, query = 49152, W = 589824, block_emb = largest, top_k scalar ignored (TOPK=5 per out_size).
extern "C" void kernel_launch(void* const* d_in, const int* in_sizes, int n_in,
                              void* d_out, int out_size)
{
    const float *query = nullptr, *W = nullptr, *bias = nullptr, *emb = nullptr;
    int ndocs = 0;
    for (int i = 0; i < n_in; i++) {
        int sz = in_sizes[i];
        if      (sz == DIM)        bias  = (const float*)d_in[i];
        else if (sz == QN * DIM)   query = (const float*)d_in[i];
        else if (sz == DIM * DIM)  W     = (const float*)d_in[i];
        else if (sz >  DIM * DIM) { emb  = (const float*)d_in[i]; ndocs = sz / DIM; }
    }
    if (!query || !W || !bias || !emb || ndocs <= 0) return;

    int ntiles = (ndocs + TILE_M - 1) / TILE_M;

    cudaFuncSetAttribute(score_topk_kernel, cudaFuncAttributeMaxDynamicSharedMemorySize, SMEM_DYN);

    qproj_kernel<<<DIM / 16, 256>>>(query, W, bias);
    score_topk_kernel<<<NBLOCKS, NTHREADS, SMEM_DYN>>>(emb, ndocs, ntiles);
    final_topk_kernel<<<QN, 128>>>((float*)d_out, NBLOCKS);
}